// round 13
// baseline (speedup 1.0000x reference)
#include <cuda_runtime.h>
#include <math.h>

#define W 1024
#define H 1024
#define NB 4
#define NPIX (NB * W * H)

#define NPASS 6
#define RT 32                       // hysteresis rows per strip
#define HBLOCKS (NB * H / RT)       // 128 strips (full width)
#define SPB (H / RT)                // 32 strips per batch
#define WPR 16                      // u64 words per row (1024 bits)
#define P (WPR + 1)

// canny tile: 32 wide x 64 tall
#define TH 64

typedef unsigned long long u64;

// ---------------- device scratch (no runtime allocation) ----------------
__device__ u64 g_fill[NB * H * WPR];    // weak-or-strong bits
__device__ u64 g_strong[NB * H * WPR];  // strong bits (grows monotonically)
__device__ int g_dirty[NPASS][HBLOCKS]; // strip changed in pass p

__constant__ int c_dy[8] = {0, -1, -1, -1, 0, 1, 1, 1};
__constant__ int c_dx[8] = {1,  1,  0, -1, -1, -1, 0, 1};

__device__ __forceinline__ int reflect1024(int t) {
    t = (t < 0) ? -t : t;
    return (t > 1023) ? (2046 - t) : t;
}
__device__ __forceinline__ int clamp1024(int t) {
    return (t < 0) ? 0 : ((t > 1023) ? 1023 : t);
}

// In-word bidirectional flood of seeds through runs of F.
__device__ __forceinline__ u64 wflood(u64 F, u64 seed) {
    u64 t = seed & F;
    u64 up = (((F + t) ^ F) & F) | t;          // toward MSB
    u64 Fr = __brevll(F), sr = __brevll(up);
    u64 tr = sr & Fr;
    u64 dn = (((Fr + tr) ^ Fr) & Fr) | tr;     // toward LSB of original
    return __brevll(dn);
}

// =====================================================================
// Kernel A: gray -> 5x5 gaussian -> sobel -> magnitude -> NMS ->
//           double threshold (bit planes out). 32x64 tile, halo 4.
//           All arithmetic identical to R2..R11 (NMS recomputes gx,gy
//           from the same Sb values with the same expression).
// =====================================================================
__global__ __launch_bounds__(256) void canny_main(const float* __restrict__ in,
                                                  float* __restrict__ magout)
{
    __shared__ float4 SgQ[TH + 8][11];     // gray, pitch 44 floats
    __shared__ float Sb[TH + 4][37];       // blurred at clamped centers
    __shared__ float Smag[TH + 2][35];     // magnitude (0 outside image)
    float* Sg = (float*)SgQ;

    const int tid = threadIdx.x;
    const int b  = blockIdx.z;
    const int y0 = blockIdx.y * TH;
    const int x0 = blockIdx.x << 5;
    const float* pr = in + (size_t)b * 3 * W * H;

    if (b == 0 && blockIdx.x == 0 && blockIdx.y == 0) {
        for (int k = tid; k < NPASS * HBLOCKS; k += 256)
            ((int*)g_dirty)[k] = 0;
    }

    const float E0 = 0.13533528323661270231f;   // exp(-2)
    const float E1 = 0.60653065971263342360f;   // exp(-0.5)
    const float gs = __fadd_rn(__fadd_rn(__fadd_rn(__fadd_rn(E0, E1), 1.0f), E1), E0);
    float g1d[5];
    g1d[0] = __fdiv_rn(E0, gs);
    g1d[1] = __fdiv_rn(E1, gs);
    g1d[2] = __fdiv_rn(1.0f, gs);
    g1d[3] = g1d[1];
    g1d[4] = g1d[0];
    float g2d[5][5];
#pragma unroll
    for (int r = 0; r < 5; ++r)
#pragma unroll
        for (int c = 0; c < 5; ++c)
            g2d[r][c] = __fmul_rn(g1d[r], g1d[c]);

    // ---- gray with reflect padding: rows y0-4 .. y0+TH+3, cols x0-4 .. x0+35 ----
    for (int k = tid; k < (TH + 8) * 40; k += 256) {
        int j = k / 40, i = k - j * 40;
        int ry = reflect1024(y0 - 4 + j);
        int rx = reflect1024(x0 - 4 + i);
        int o = ry * W + rx;
        float r = pr[o], g = pr[o + W * H], bl = pr[o + 2 * W * H];
        Sg[j * 44 + i] = __fadd_rn(__fadd_rn(__fmul_rn(0.299f, r), __fmul_rn(0.587f, g)),
                                   __fmul_rn(0.114f, bl));
    }
    __syncthreads();

    // ---- direct 5x5 gaussian at clamped (edge-pad) centers ----
    const bool interior = (blockIdx.x >= 1) && (blockIdx.x <= 30) &&
                          (blockIdx.y >= 1) && (blockIdx.y <= (H / TH) - 2);
    if (interior) {
        for (int k = tid; k < (TH + 4) * 9; k += 256) {
            int j = k / 9, q = k - j * 9;
            float acc0 = 0.f, acc1 = 0.f, acc2 = 0.f, acc3 = 0.f;
#pragma unroll
            for (int r = 0; r < 5; ++r) {
                float4 A = SgQ[j + r][q];
                float4 B = SgQ[j + r][q + 1];
                float v[8] = {A.x, A.y, A.z, A.w, B.x, B.y, B.z, B.w};
#pragma unroll
                for (int c = 0; c < 5; ++c) {
                    acc0 = fmaf(g2d[r][c], v[c],     acc0);
                    acc1 = fmaf(g2d[r][c], v[c + 1], acc1);
                    acc2 = fmaf(g2d[r][c], v[c + 2], acc2);
                    acc3 = fmaf(g2d[r][c], v[c + 3], acc3);
                }
            }
            Sb[j][4 * q + 0] = acc0;
            Sb[j][4 * q + 1] = acc1;
            Sb[j][4 * q + 2] = acc2;
            Sb[j][4 * q + 3] = acc3;
        }
    } else {
        for (int k = tid; k < (TH + 4) * 36; k += 256) {
            int j = k / 36, i = k - j * 36;
            int sj = clamp1024(y0 - 2 + j) - y0 + 4;
            int si = clamp1024(x0 - 2 + i) - x0 + 4;
            float acc = 0.0f;
#pragma unroll
            for (int r = 0; r < 5; ++r)
#pragma unroll
                for (int c = 0; c < 5; ++c)
                    acc = fmaf(g2d[r][c], Sg[(sj - 2 + r) * 44 + (si - 2 + c)], acc);
            Sb[j][i] = acc;
        }
    }
    __syncthreads();

    // ---- sobel + magnitude over rows y0-1 .. y0+TH ----
    for (int k = tid; k < (TH + 2) * 34; k += 256) {
        int j = k / 34, i = k - j * 34;
        float a00 = Sb[j][i],     a01 = Sb[j][i + 1],     a02 = Sb[j][i + 2];
        float a10 = Sb[j + 1][i],                         a12 = Sb[j + 1][i + 2];
        float a20 = Sb[j + 2][i], a21 = Sb[j + 2][i + 1], a22 = Sb[j + 2][i + 2];
        float gx = __fadd_rn(__fadd_rn(__fadd_rn(__fadd_rn(__fadd_rn(
                     -a00, a02), __fmul_rn(-2.0f, a10)), __fmul_rn(2.0f, a12)), -a20), a22);
        float gy = __fadd_rn(__fadd_rn(__fadd_rn(__fadd_rn(__fadd_rn(
                     -a00, __fmul_rn(-2.0f, a01)), -a02), a20), __fmul_rn(2.0f, a21)), a22);
        float s = __fadd_rn(__fadd_rn(__fmul_rn(gx, gx), __fmul_rn(gy, gy)), 1e-6f);
        float m = __fsqrt_rn(s);
        int yy = y0 - 1 + j, xx = x0 - 1 + i;
        bool inb = ((unsigned)yy < 1024u) && ((unsigned)xx < 1024u);
        Smag[j][i] = inb ? m : 0.0f;
    }
    __syncthreads();

    // ---- NMS + double threshold; emit magnitude + fill/strong bit planes ----
    unsigned* fillp   = (unsigned*)g_fill;
    unsigned* strongp = (unsigned*)g_strong;
    const float T22LO = 0.41421356237309515f * 0.999f;
    const float T22HI = 0.41421356237309515f * 1.001f;
    const float T67LO = 2.41421356237309515f * 0.999f;
    const float T67HI = 2.41421356237309515f * 1.001f;
    for (int k = tid; k < TH * 32; k += 256) {
        int j = k >> 5, i = k & 31;
        float m  = Smag[j + 1][i + 1];
        // recompute gx,gy for this pixel from the same Sb values, same expression
        float a00 = Sb[j + 1][i + 1], a01 = Sb[j + 1][i + 2], a02 = Sb[j + 1][i + 3];
        float a10 = Sb[j + 2][i + 1],                          a12 = Sb[j + 2][i + 3];
        float a20 = Sb[j + 3][i + 1], a21 = Sb[j + 3][i + 2], a22 = Sb[j + 3][i + 3];
        float gx = __fadd_rn(__fadd_rn(__fadd_rn(__fadd_rn(__fadd_rn(
                     -a00, a02), __fmul_rn(-2.0f, a10)), __fmul_rn(2.0f, a12)), -a20), a22);
        float gy = __fadd_rn(__fadd_rn(__fadd_rn(__fadd_rn(__fadd_rn(
                     -a00, __fmul_rn(-2.0f, a01)), -a02), a20), __fmul_rn(2.0f, a21)), a22);
        float ax = fabsf(gx), ay = fabsf(gy);
        bool gxn = gx < 0.0f, gyn = gy < 0.0f;
        int pos;
        if (ay < ax * T22LO) {
            pos = gxn ? 4 : 0;
        } else if (ay > ax * T67HI) {
            pos = gyn ? 6 : 2;
        } else if (ay > ax * T22HI && ay < ax * T67LO) {
            pos = gyn ? (gxn ? 5 : 7) : (gxn ? 3 : 1);
        } else {
            float ang = __fmul_rn(atan2f(gy, gx), 57.29577951308232087680f);
            int q = (int)rintf(__fdiv_rn(ang, 45.0f));
            pos = q & 7;
        }
        int neg = pos ^ 4;
        float np_ = Smag[j + 1 + c_dy[pos]][i + 1 + c_dx[pos]];
        float nn_ = Smag[j + 1 + c_dy[neg]][i + 1 + c_dx[neg]];
        float mo = (fminf(__fadd_rn(m, -np_), __fadd_rn(m, -nn_)) > 0.0f) ? m : 0.0f;
        int y = y0 + j;
        magout[(b * H + y) * W + x0 + i] = mo;
        unsigned fm = __ballot_sync(0xffffffffu, mo > 0.1f);
        unsigned sm = __ballot_sync(0xffffffffu, mo > 0.2f);
        if (i == 0) {
            int wi = (b * H + y) * (2 * WPR) + (x0 >> 5);
            fillp[wi] = fm;
            strongp[wi] = sm;
        }
    }
}

// =====================================================================
// Kernel B: one bit-parallel hysteresis pass over full-width 32-row
// strips, 512 threads (one u64 word each). 3 Jacobi steps per barrier
// (monotone; a quiescent barrier group read only converged values =>
// exact fixed point). Pass p>0 skips strips whose inputs are unchanged.
// =====================================================================
__global__ __launch_bounds__(512) void hyst_pass(int pass)
{
    const int t = blockIdx.x;                    // strip id
    const int s = t & (SPB - 1);                 // strip within batch
    if (pass > 0) {
        const int* prev = g_dirty[pass - 1];
        bool run = prev[t] != 0;
        if (s > 0)       run |= prev[t - 1] != 0;
        if (s < SPB - 1) run |= prev[t + 1] != 0;
        if (!run) return;
    }

    __shared__ u64 sS[(RT + 2) * P];
    __shared__ u64 sF[(RT + 2) * P];
    const int tid = threadIdx.x;
    const int b  = t / SPB;
    const int y0 = s * RT;

    // load halo strip (rows y0-1 .. y0+RT)
    for (int k = tid; k < (RT + 2) * WPR; k += 512) {
        int r = k >> 4, w = k & (WPR - 1);
        int gy = y0 + r - 1;
        u64 f = 0ull, sv = 0ull;
        if ((unsigned)gy < (unsigned)H) {
            int o = (b * H + gy) * WPR + w;
            f = g_fill[o];
            sv = g_strong[o];
        }
        sF[r * P + w] = f;
        sS[r * P + w] = sv;
    }
    __syncthreads();

    const int w = tid & 15;
    const int r = (tid >> 4) + 1;               // rows 1..32, one per thread
    const u64 F = sF[r * P + w];
    u64 S = sS[r * P + w];

    int any = 0;
    for (;;) {
        int ch = 0;
#pragma unroll
        for (int st = 0; st < 3; ++st) {
            if (F != S) {
                u64 above = sS[(r - 1) * P + w];
                u64 below = sS[(r + 1) * P + w];
                u64 X = above | S | below;
                u64 XL = (w > 0)
                    ? (sS[(r - 1) * P + w - 1] | sS[r * P + w - 1] | sS[(r + 1) * P + w - 1])
                    : 0ull;
                u64 XR = (w < WPR - 1)
                    ? (sS[(r - 1) * P + w + 1] | sS[r * P + w + 1] | sS[(r + 1) * P + w + 1])
                    : 0ull;
                u64 d = X | (X << 1) | (XL >> 63) | (X >> 1) | (XR << 63);
                u64 ns = wflood(F, (F & d) | S);
                if (ns != S) {
                    S = ns;
                    sS[r * P + w] = ns;
                    ch = 1;
                }
            }
        }
        any |= ch;
        if (!__syncthreads_or(ch)) break;
    }

    if (__syncthreads_or(any)) {
        g_strong[(b * H + y0 + r - 1) * WPR + w] = S;
        if (tid == 0) g_dirty[pass][t] = 1;
    }
}

// =====================================================================
// Kernel C: edges = 1.0 where strong else 0.0
// =====================================================================
__global__ __launch_bounds__(256) void edges_final(float* __restrict__ e)
{
    int i = blockIdx.x * 256 + threadIdx.x;       // over NPIX/4
    unsigned wrd = ((const unsigned*)g_strong)[i >> 3];
    int sh = (i & 7) * 4;
    float4 f;
    f.x = (wrd >> (sh + 0)) & 1u ? 1.0f : 0.0f;
    f.y = (wrd >> (sh + 1)) & 1u ? 1.0f : 0.0f;
    f.z = (wrd >> (sh + 2)) & 1u ? 1.0f : 0.0f;
    f.w = (wrd >> (sh + 3)) & 1u ? 1.0f : 0.0f;
    ((float4*)e)[i] = f;
}

// =====================================================================
extern "C" void kernel_launch(void* const* d_in, const int* in_sizes, int n_in,
                              void* d_out, int out_size)
{
    (void)in_sizes; (void)n_in; (void)out_size;
    const float* x = (const float*)d_in[0];
    float* out = (float*)d_out;          // magnitude (4,1,1024,1024)
    float* edges = out + (size_t)NPIX;   // edges     (4,1,1024,1024)

    dim3 grid(32, H / TH, NB);
    canny_main<<<grid, 256>>>(x, out);

    for (int p = 0; p < NPASS; ++p)
        hyst_pass<<<HBLOCKS, 512>>>(p);

    edges_final<<<NPIX / 1024, 256>>>(edges);
}

// round 14
// speedup vs baseline: 1.0056x; 1.0056x over previous
#include <cuda_runtime.h>
#include <math.h>

#define W 1024
#define H 1024
#define NB 4
#define NPIX (NB * W * H)

#define NPASS 6
#define RT 16                       // hysteresis rows per strip
#define HBLOCKS (NB * H / RT)       // 256 strips (full width)
#define SPB 64                      // strips per batch
#define WPR 16                      // u64 words per row (1024 bits)
#define P (WPR + 1)

typedef unsigned long long u64;

// ---------------- device scratch (no runtime allocation) ----------------
__device__ u64 g_fill[NB * H * WPR];    // weak-or-strong bits
__device__ u64 g_strong[NB * H * WPR];  // strong bits (grows monotonically)
__device__ int g_dirty[NPASS][HBLOCKS]; // bit0: top row changed, bit1: bottom row changed

__constant__ int c_dy[8] = {0, -1, -1, -1, 0, 1, 1, 1};
__constant__ int c_dx[8] = {1,  1,  0, -1, -1, -1, 0, 1};

__device__ __forceinline__ int reflect1024(int t) {
    t = (t < 0) ? -t : t;
    return (t > 1023) ? (2046 - t) : t;
}
__device__ __forceinline__ int clamp1024(int t) {
    return (t < 0) ? 0 : ((t > 1023) ? 1023 : t);
}

// In-word bidirectional flood of seeds through runs of F.
__device__ __forceinline__ u64 wflood(u64 F, u64 seed) {
    u64 t = seed & F;
    u64 up = (((F + t) ^ F) & F) | t;          // toward MSB
    u64 Fr = __brevll(F), sr = __brevll(up);
    u64 tr = sr & Fr;
    u64 dn = (((Fr + tr) ^ Fr) & Fr) | tr;     // toward LSB of original
    return __brevll(dn);
}

// =====================================================================
// Kernel A: gray -> 5x5 gaussian -> sobel -> magnitude -> NMS ->
//           double threshold (bit planes out). 32x32 tile, halo 4.
//           All per-output arithmetic identical to R2..R11; sobel stage
//           is 4-wide vectorized (same expression per output).
// =====================================================================
__global__ __launch_bounds__(256) void canny_main(const float* __restrict__ in,
                                                  float* __restrict__ magout)
{
    __shared__ float4 SgQ[40][11];   // gray, pitch 44 floats
    __shared__ float4 Sb4[36][10];   // blurred, pitch 40 floats (36 cols used)
    __shared__ float Smag[34][35];
    __shared__ float Sgx[34][35];
    __shared__ float Sgy[34][35];
    float* Sg = (float*)SgQ;
    float* Sb = (float*)Sb4;         // Sb[j*40 + i]

    const int tid = threadIdx.x;
    const int b  = blockIdx.z;
    const int y0 = blockIdx.y << 5;
    const int x0 = blockIdx.x << 5;
    const float* pr = in + (size_t)b * 3 * W * H;

    if (b == 0 && blockIdx.x == 0 && blockIdx.y == 0) {
        for (int k = tid; k < NPASS * HBLOCKS; k += 256)
            ((int*)g_dirty)[k] = 0;
    }

    const float E0 = 0.13533528323661270231f;   // exp(-2)
    const float E1 = 0.60653065971263342360f;   // exp(-0.5)
    const float gs = __fadd_rn(__fadd_rn(__fadd_rn(__fadd_rn(E0, E1), 1.0f), E1), E0);
    float g1d[5];
    g1d[0] = __fdiv_rn(E0, gs);
    g1d[1] = __fdiv_rn(E1, gs);
    g1d[2] = __fdiv_rn(1.0f, gs);
    g1d[3] = g1d[1];
    g1d[4] = g1d[0];
    float g2d[5][5];
#pragma unroll
    for (int r = 0; r < 5; ++r)
#pragma unroll
        for (int c = 0; c < 5; ++c)
            g2d[r][c] = __fmul_rn(g1d[r], g1d[c]);

    // ---- gray with reflect padding ----
    for (int k = tid; k < 40 * 40; k += 256) {
        int j = k / 40, i = k - j * 40;
        int ry = reflect1024(y0 - 4 + j);
        int rx = reflect1024(x0 - 4 + i);
        int o = ry * W + rx;
        float r = pr[o], g = pr[o + W * H], bl = pr[o + 2 * W * H];
        Sg[j * 44 + i] = __fadd_rn(__fadd_rn(__fmul_rn(0.299f, r), __fmul_rn(0.587f, g)),
                                   __fmul_rn(0.114f, bl));
    }
    __syncthreads();

    // ---- direct 5x5 gaussian at clamped (edge-pad) centers ----
    const bool interior = (blockIdx.x >= 1) && (blockIdx.x <= 30) &&
                          (blockIdx.y >= 1) && (blockIdx.y <= 30);
    if (interior) {
        for (int k = tid; k < 36 * 9; k += 256) {
            int j = k / 9, q = k - j * 9;
            float acc0 = 0.f, acc1 = 0.f, acc2 = 0.f, acc3 = 0.f;
#pragma unroll
            for (int r = 0; r < 5; ++r) {
                float4 A = SgQ[j + r][q];
                float4 B = SgQ[j + r][q + 1];
                float v[8] = {A.x, A.y, A.z, A.w, B.x, B.y, B.z, B.w};
#pragma unroll
                for (int c = 0; c < 5; ++c) {
                    acc0 = fmaf(g2d[r][c], v[c],     acc0);
                    acc1 = fmaf(g2d[r][c], v[c + 1], acc1);
                    acc2 = fmaf(g2d[r][c], v[c + 2], acc2);
                    acc3 = fmaf(g2d[r][c], v[c + 3], acc3);
                }
            }
            float4 o4 = make_float4(acc0, acc1, acc2, acc3);
            *((float4*)(Sb + j * 40 + 4 * q)) = o4;
        }
    } else {
        for (int k = tid; k < 36 * 36; k += 256) {
            int j = k / 36, i = k - j * 36;
            int sj = clamp1024(y0 - 2 + j) - y0 + 4;
            int si = clamp1024(x0 - 2 + i) - x0 + 4;
            float acc = 0.0f;
#pragma unroll
            for (int r = 0; r < 5; ++r)
#pragma unroll
                for (int c = 0; c < 5; ++c)
                    acc = fmaf(g2d[r][c], Sg[(sj - 2 + r) * 44 + (si - 2 + c)], acc);
            Sb[j * 40 + i] = acc;
        }
    }
    __syncthreads();

    // ---- sobel + magnitude, 4-wide vector units (same per-output math) ----
    for (int k = tid; k < 34 * 9; k += 256) {
        int j = k / 9, q = k - j * 9;            // output cols 4q..4q+3 (mask >=34)
        float4 A0 = Sb4[j][q],     B0 = Sb4[j][q + 1];
        float4 A1 = Sb4[j + 1][q], B1 = Sb4[j + 1][q + 1];
        float4 A2 = Sb4[j + 2][q], B2 = Sb4[j + 2][q + 1];
        float r0[8] = {A0.x, A0.y, A0.z, A0.w, B0.x, B0.y, B0.z, B0.w};
        float r1[8] = {A1.x, A1.y, A1.z, A1.w, B1.x, B1.y, B1.z, B1.w};
        float r2[8] = {A2.x, A2.y, A2.z, A2.w, B2.x, B2.y, B2.z, B2.w};
#pragma unroll
        for (int c4 = 0; c4 < 4; ++c4) {
            int i = 4 * q + c4;
            if (i < 34) {
                float a00 = r0[c4], a01 = r0[c4 + 1], a02 = r0[c4 + 2];
                float a10 = r1[c4],                   a12 = r1[c4 + 2];
                float a20 = r2[c4], a21 = r2[c4 + 1], a22 = r2[c4 + 2];
                float gx = __fadd_rn(__fadd_rn(__fadd_rn(__fadd_rn(__fadd_rn(
                             -a00, a02), __fmul_rn(-2.0f, a10)), __fmul_rn(2.0f, a12)), -a20), a22);
                float gy = __fadd_rn(__fadd_rn(__fadd_rn(__fadd_rn(__fadd_rn(
                             -a00, __fmul_rn(-2.0f, a01)), -a02), a20), __fmul_rn(2.0f, a21)), a22);
                float s = __fadd_rn(__fadd_rn(__fmul_rn(gx, gx), __fmul_rn(gy, gy)), 1e-6f);
                float m = __fsqrt_rn(s);
                int yy = y0 - 1 + j, xx = x0 - 1 + i;
                bool inb = ((unsigned)yy < 1024u) && ((unsigned)xx < 1024u);
                Smag[j][i] = inb ? m : 0.0f;
                Sgx[j][i] = gx;
                Sgy[j][i] = gy;
            }
        }
    }
    __syncthreads();

    // ---- NMS + double threshold; emit magnitude + fill/strong bit planes ----
    unsigned* fillp   = (unsigned*)g_fill;
    unsigned* strongp = (unsigned*)g_strong;
    const float T22LO = 0.41421356237309515f * 0.999f;
    const float T22HI = 0.41421356237309515f * 1.001f;
    const float T67LO = 2.41421356237309515f * 0.999f;
    const float T67HI = 2.41421356237309515f * 1.001f;
    for (int k = tid; k < 1024; k += 256) {
        int j = k >> 5, i = k & 31;
        float m  = Smag[j + 1][i + 1];
        float gx = Sgx[j + 1][i + 1];
        float gy = Sgy[j + 1][i + 1];
        float ax = fabsf(gx), ay = fabsf(gy);
        bool gxn = gx < 0.0f, gyn = gy < 0.0f;
        int pos;
        if (ay < ax * T22LO) {
            pos = gxn ? 4 : 0;
        } else if (ay > ax * T67HI) {
            pos = gyn ? 6 : 2;
        } else if (ay > ax * T22HI && ay < ax * T67LO) {
            pos = gyn ? (gxn ? 5 : 7) : (gxn ? 3 : 1);
        } else {
            float ang = __fmul_rn(atan2f(gy, gx), 57.29577951308232087680f);
            int q = (int)rintf(__fdiv_rn(ang, 45.0f));
            pos = q & 7;
        }
        int neg = pos ^ 4;
        float np_ = Smag[j + 1 + c_dy[pos]][i + 1 + c_dx[pos]];
        float nn_ = Smag[j + 1 + c_dy[neg]][i + 1 + c_dx[neg]];
        float mo = (fminf(__fadd_rn(m, -np_), __fadd_rn(m, -nn_)) > 0.0f) ? m : 0.0f;
        int y = y0 + j;
        magout[(b * H + y) * W + x0 + i] = mo;
        unsigned fm = __ballot_sync(0xffffffffu, mo > 0.1f);
        unsigned sm = __ballot_sync(0xffffffffu, mo > 0.2f);
        if (i == 0) {
            int wi = (b * H + y) * (2 * WPR) + (x0 >> 5);
            fillp[wi] = fm;
            strongp[wi] = sm;
        }
    }
}

// =====================================================================
// Kernel B: one bit-parallel hysteresis pass over full-width 16-row
// strips. Pass p>0 runs strip t only if a halo row it reads changed in
// pass p-1: neighbor-above's bottom row or neighbor-below's top row
// (skipped => inputs unchanged => re-run would be a no-op; exact).
// Jacobi sweeps with in-word wflood; quiescent sweep => exact fixed
// point of the basic operator => deterministic, bit-identical output.
// =====================================================================
__global__ __launch_bounds__(256) void hyst_pass(int pass)
{
    const int t = blockIdx.x;                    // strip id
    const int s = t & (SPB - 1);                 // strip within batch
    if (pass > 0) {
        const int* prev = g_dirty[pass - 1];
        bool run = false;
        if (s > 0)       run |= (prev[t - 1] & 2) != 0;   // above's bottom row
        if (s < SPB - 1) run |= (prev[t + 1] & 1) != 0;   // below's top row
        if (!run) return;
    }

    __shared__ u64 sS[(RT + 2) * P];
    __shared__ u64 sF[(RT + 2) * P];
    __shared__ int s_top, s_bot;
    const int tid = threadIdx.x;
    const int b  = t >> 6;
    const int y0 = s * RT;

    if (tid == 0) { s_top = 0; s_bot = 0; }

    // load halo strip (rows y0-1 .. y0+RT)
    for (int k = tid; k < (RT + 2) * WPR; k += 256) {
        int r = k >> 4, w = k & (WPR - 1);
        int gy = y0 + r - 1;
        u64 f = 0ull, sv = 0ull;
        if ((unsigned)gy < (unsigned)H) {
            int o = (b * H + gy) * WPR + w;
            f = g_fill[o];
            sv = g_strong[o];
        }
        sF[r * P + w] = f;
        sS[r * P + w] = sv;
    }
    __syncthreads();

    const int w = tid & 15;
    const int r = (tid >> 4) + 1;               // rows 1..16, one per thread
    const u64 F = sF[r * P + w];
    u64 S = sS[r * P + w];
    const u64 S0 = S;

    int any = 0;
    for (;;) {
        int ch = 0;
        if (F != S) {
            u64 above = sS[(r - 1) * P + w];
            u64 below = sS[(r + 1) * P + w];
            u64 X = above | S | below;
            u64 XL = (w > 0)
                ? (sS[(r - 1) * P + w - 1] | sS[r * P + w - 1] | sS[(r + 1) * P + w - 1])
                : 0ull;
            u64 XR = (w < WPR - 1)
                ? (sS[(r - 1) * P + w + 1] | sS[r * P + w + 1] | sS[(r + 1) * P + w + 1])
                : 0ull;
            u64 d = X | (X << 1) | (XL >> 63) | (X >> 1) | (XR << 63);
            u64 ns = wflood(F, (F & d) | S);
            if (ns != S) {
                S = ns;
                sS[r * P + w] = ns;
                ch = 1;
            }
        }
        any |= ch;
        if (!__syncthreads_or(ch)) break;
    }

    if (S != S0) {
        if (r == 1)  s_top = 1;                  // benign race: all write 1
        if (r == RT) s_bot = 1;
    }

    if (__syncthreads_or(any)) {
        g_strong[(b * H + y0 + r - 1) * WPR + w] = S;
        if (tid == 0) g_dirty[pass][t] = s_top | (s_bot << 1);
    }
}

// =====================================================================
// Kernel C: edges = 1.0 where strong else 0.0
// =====================================================================
__global__ __launch_bounds__(256) void edges_final(float* __restrict__ e)
{
    int i = blockIdx.x * 256 + threadIdx.x;       // over NPIX/4
    unsigned wrd = ((const unsigned*)g_strong)[i >> 3];
    int sh = (i & 7) * 4;
    float4 f;
    f.x = (wrd >> (sh + 0)) & 1u ? 1.0f : 0.0f;
    f.y = (wrd >> (sh + 1)) & 1u ? 1.0f : 0.0f;
    f.z = (wrd >> (sh + 2)) & 1u ? 1.0f : 0.0f;
    f.w = (wrd >> (sh + 3)) & 1u ? 1.0f : 0.0f;
    ((float4*)e)[i] = f;
}

// =====================================================================
extern "C" void kernel_launch(void* const* d_in, const int* in_sizes, int n_in,
                              void* d_out, int out_size)
{
    (void)in_sizes; (void)n_in; (void)out_size;
    const float* x = (const float*)d_in[0];
    float* out = (float*)d_out;          // magnitude (4,1,1024,1024)
    float* edges = out + (size_t)NPIX;   // edges     (4,1,1024,1024)

    dim3 grid(32, 32, NB);
    canny_main<<<grid, 256>>>(x, out);

    for (int p = 0; p < NPASS; ++p)
        hyst_pass<<<HBLOCKS, 256>>>(p);

    edges_final<<<NPIX / 1024, 256>>>(edges);
}